// round 14
// baseline (speedup 1.0000x reference)
#include <cuda_runtime.h>
#include <cuda_bf16.h>

#define Nn 50000
#define Ee 800000
#define Dd 256
#define Fin 64
#define Bg 1000
#define BN_EPS 1e-5f

// ---------------- scratch (device globals; no allocation) ----------------
__device__ float g_mm[Nn * Dd];      // matmul output
__device__ float g_agg[Nn * Dd];     // aggregated + bias
__device__ float g_h[Nn * Dd];       // layer activation
__device__ int   g_cnt[Nn];          // in-degree (no self loop)
__device__ float g_dinv[Nn];         // rsqrt(deg+1)
__device__ int   g_off[Nn + 1];      // CSR row offsets
__device__ int   g_cur[Nn];          // scatter cursors
__device__ int   g_ssrc[Ee];         // src ids sorted by dst
__device__ float g_coef[Ee];         // dinv[src]*dinv[dst] sorted by dst
__device__ float g_sum[Dd];
__device__ float g_sumsq[Dd];

// ---------------- graph preprocessing ----------------
__global__ void k_zero_graph() {
    int i = blockIdx.x * blockDim.x + threadIdx.x;
    if (i < Nn) { g_cnt[i] = 0; g_cur[i] = 0; }
}

__global__ void k_degree(const int* __restrict__ ei) {
    int e = blockIdx.x * blockDim.x + threadIdx.x;
    if (e < Ee) atomicAdd(&g_cnt[ei[Ee + e]], 1);
}

__global__ void k_scan() {
    // single block, 1024 threads: exclusive scan of g_cnt -> g_off, plus dinv
    const int T = 1024;
    const int chunk = (Nn + T - 1) / T;
    __shared__ int s[T];
    int t = threadIdx.x;
    int beg = t * chunk;
    int end = beg + chunk; if (end > Nn) end = Nn;
    int loc = 0;
    for (int i = beg; i < end; i++) loc += g_cnt[i];
    s[t] = loc;
    __syncthreads();
    for (int d = 1; d < T; d <<= 1) {
        int v = (t >= d) ? s[t - d] : 0;
        __syncthreads();
        s[t] += v;
        __syncthreads();
    }
    int prefix = (t == 0) ? 0 : s[t - 1];
    for (int i = beg; i < end; i++) {
        g_off[i] = prefix;
        prefix += g_cnt[i];
    }
    if (t == T - 1) g_off[Nn] = prefix;
    for (int i = t; i < Nn; i += T) g_dinv[i] = rsqrtf(1.0f + (float)g_cnt[i]);
}

__global__ void k_scatter(const int* __restrict__ ei) {
    int e = blockIdx.x * blockDim.x + threadIdx.x;
    if (e >= Ee) return;
    int s = ei[e];
    int d = ei[Ee + e];
    int pos = g_off[d] + atomicAdd(&g_cur[d], 1);
    g_ssrc[pos] = s;
    g_coef[pos] = g_dinv[s] * g_dinv[d];
}

// ---------------- SGEMM: C[N,Dd] = A[N,K] @ W[K,Dd] ----------------
// BM=128, BN=128, BK=16, 256 threads, 8x8 micro-tile.
__global__ __launch_bounds__(256, 2)
void k_gemm(const float* __restrict__ x, const float* __restrict__ W, int K, int useX) {
    const int BM = 128, BNt = 128, BK = 16;
    __shared__ float As[BK][BM];
    __shared__ float Bs[BK][BNt];

    int bn = blockIdx.x;      // 0..1
    int bm = blockIdx.y;      // row tile
    int tid = threadIdx.x;
    int tx = tid & 15, ty = tid >> 4;
    int rowBase = bm * BM;

    const float* Abase = useX ? x : g_h;

    float acc[8][8];
#pragma unroll
    for (int i = 0; i < 8; i++)
#pragma unroll
        for (int j = 0; j < 8; j++) acc[i][j] = 0.0f;

    for (int k0 = 0; k0 < K; k0 += BK) {
        // load A tile: 128 rows x 16 cols = 512 float4
#pragma unroll
        for (int l = 0; l < 2; l++) {
            int idx = tid * 2 + l;        // 0..511
            int m = idx >> 2;             // 0..127
            int k4 = idx & 3;             // 0..3
            int grow = rowBase + m;
            float4 v = make_float4(0.f, 0.f, 0.f, 0.f);
            if (grow < Nn)
                v = *(const float4*)&Abase[(size_t)grow * K + k0 + k4 * 4];
            As[k4 * 4 + 0][m] = v.x;
            As[k4 * 4 + 1][m] = v.y;
            As[k4 * 4 + 2][m] = v.z;
            As[k4 * 4 + 3][m] = v.w;
        }
        // load B tile: 16 x 128 = 512 float4
#pragma unroll
        for (int l = 0; l < 2; l++) {
            int idx = tid * 2 + l;
            int k = idx >> 5;             // 0..15
            int n4 = idx & 31;            // 0..31
            float4 v = *(const float4*)&W[(size_t)(k0 + k) * Dd + bn * BNt + n4 * 4];
            *(float4*)&Bs[k][n4 * 4] = v;
        }
        __syncthreads();
#pragma unroll
        for (int k = 0; k < BK; k++) {
            float ra[8], rb[8];
#pragma unroll
            for (int i = 0; i < 8; i++) ra[i] = As[k][ty * 8 + i];
#pragma unroll
            for (int j = 0; j < 8; j++) rb[j] = Bs[k][tx * 8 + j];
#pragma unroll
            for (int i = 0; i < 8; i++)
#pragma unroll
                for (int j = 0; j < 8; j++) acc[i][j] += ra[i] * rb[j];
        }
        __syncthreads();
    }
#pragma unroll
    for (int i = 0; i < 8; i++) {
        int grow = rowBase + ty * 8 + i;
        if (grow < Nn) {
#pragma unroll
            for (int j = 0; j < 8; j += 4) {
                float4 v = make_float4(acc[i][j], acc[i][j + 1], acc[i][j + 2], acc[i][j + 3]);
                *(float4*)&g_mm[(size_t)grow * Dd + bn * BNt + tx * 8 + j] = v;
            }
        }
    }
}

// ---------------- aggregation: agg = D^-1/2 (A+I) D^-1/2 (mm) + b ----------------
// 64 threads (float4 lanes) per node, 4 nodes per block.
__global__ void k_aggregate(const float* __restrict__ bias) {
    int node = blockIdx.x * 4 + (threadIdx.x >> 6);
    int lane = threadIdx.x & 63;
    if (node >= Nn) return;

    const float4* mmv = (const float4*)g_mm;
    float di = g_dinv[node];
    float4 acc = mmv[(size_t)node * 64 + lane];
    float sc = di * di;
    acc.x *= sc; acc.y *= sc; acc.z *= sc; acc.w *= sc;

    int s0 = g_off[node], s1 = g_off[node + 1];
    for (int k = s0; k < s1; k++) {
        int s = g_ssrc[k];
        float c = g_coef[k];
        float4 v = mmv[(size_t)s * 64 + lane];
        acc.x += c * v.x; acc.y += c * v.y; acc.z += c * v.z; acc.w += c * v.w;
    }
    float4 bb = ((const float4*)bias)[lane];
    acc.x += bb.x; acc.y += bb.y; acc.z += bb.z; acc.w += bb.w;
    ((float4*)g_agg)[(size_t)node * 64 + lane] = acc;
}

// ---------------- batch-norm ----------------
__global__ void k_zero_stats() {
    int t = threadIdx.x;
    if (t < Dd) { g_sum[t] = 0.f; g_sumsq[t] = 0.f; }
}

__global__ void k_stats() {
    // each block handles 64 rows, thread = channel
    int f = threadIdx.x;               // 0..255
    int r0 = blockIdx.x * 64;
    int r1 = r0 + 64; if (r1 > Nn) r1 = Nn;
    float sm = 0.f, sq = 0.f;
    for (int r = r0; r < r1; r++) {
        float v = g_agg[(size_t)r * Dd + f];
        sm += v;
        sq += v * v;
    }
    atomicAdd(&g_sum[f], sm);
    atomicAdd(&g_sumsq[f], sq);
}

__global__ void k_norm_tanh(const float* __restrict__ gamma, const float* __restrict__ beta) {
    int idx = blockIdx.x * blockDim.x + threadIdx.x;   // over Nn*64 float4
    if (idx >= Nn * 64) return;
    int c4 = idx & 63;
    int f = c4 * 4;
    float4 v = ((const float4*)g_agg)[idx];
    const float invN = 1.0f / (float)Nn;
    float r[4] = {v.x, v.y, v.z, v.w};
#pragma unroll
    for (int j = 0; j < 4; j++) {
        float mu = g_sum[f + j] * invN;
        float var = g_sumsq[f + j] * invN - mu * mu;
        float sc = gamma[f + j] * rsqrtf(var + BN_EPS);
        r[j] = tanhf((r[j] - mu) * sc + beta[f + j]);
    }
    ((float4*)g_h)[idx] = make_float4(r[0], r[1], r[2], r[3]);
}

// ---------------- pooling + head ----------------
__device__ __forceinline__ int lower_bound_dev(const int* a, int n, int key) {
    int lo = 0, hi = n;
    while (lo < hi) {
        int mid = (lo + hi) >> 1;
        if (a[mid] < key) lo = mid + 1; else hi = mid;
    }
    return lo;
}

__global__ void k_pool(const int* __restrict__ batch, float* __restrict__ hidden) {
    __shared__ int s_lo, s_hi;
    int g = blockIdx.x;
    int f = threadIdx.x;      // 0..255
    if (f == 0) s_lo = lower_bound_dev(batch, Nn, g);
    if (f == 1) s_hi = lower_bound_dev(batch, Nn, g + 1);
    __syncthreads();
    int lo = s_lo, hi = s_hi;
    float mx = -3.4e38f, sm = 0.f;
    for (int n = lo; n < hi; n++) {
        float v = g_h[(size_t)n * Dd + f];
        mx = fmaxf(mx, v);
        sm += v;
    }
    float cnt = (float)(hi - lo);
    hidden[(size_t)g * 512 + f] = mx;
    hidden[(size_t)g * 512 + 256 + f] = sm / cnt;
}

__global__ void k_head(const float* __restrict__ hidden, const float* __restrict__ Wout,
                       const float* __restrict__ bout, float* __restrict__ out) {
    __shared__ float sm[512];
    int g = blockIdx.x;
    int t = threadIdx.x;
    sm[t] = hidden[(size_t)g * 512 + t] * Wout[t];
    __syncthreads();
    for (int s = 256; s > 0; s >>= 1) {
        if (t < s) sm[t] += sm[t + s];
        __syncthreads();
    }
    if (t == 0) out[g] = sm[0] + bout[0];
}

// ---------------- launch ----------------
extern "C" void kernel_launch(void* const* d_in, const int* in_sizes, int n_in,
                              void* d_out, int out_size) {
    const float* x     = (const float*)d_in[0];
    const int*   ei    = (const int*)d_in[1];
    const int*   batch = (const int*)d_in[2];
    const float* W[4]   = {(const float*)d_in[4], (const float*)d_in[6],
                           (const float*)d_in[8], (const float*)d_in[10]};
    const float* bia[4] = {(const float*)d_in[5], (const float*)d_in[7],
                           (const float*)d_in[9], (const float*)d_in[11]};
    const float* gam[4] = {(const float*)d_in[12], (const float*)d_in[14],
                           (const float*)d_in[16], (const float*)d_in[18]};
    const float* bet[4] = {(const float*)d_in[13], (const float*)d_in[15],
                           (const float*)d_in[17], (const float*)d_in[19]};
    const float* Wout = (const float*)d_in[20];
    const float* bout = (const float*)d_in[21];

    float* out    = (float*)d_out;        // [Bg]
    float* hidden = out + Bg;             // [Bg, 512]

    // graph preprocessing (CSR build)
    k_zero_graph<<<(Nn + 255) / 256, 256>>>();
    k_degree<<<(Ee + 255) / 256, 256>>>(ei);
    k_scan<<<1, 1024>>>();
    k_scatter<<<(Ee + 255) / 256, 256>>>(ei);

    dim3 gemmGrid(Dd / 128, (Nn + 127) / 128);

    for (int l = 0; l < 4; l++) {
        int K = (l == 0) ? Fin : Dd;
        int useX = (l == 0) ? 1 : 0;
        k_gemm<<<gemmGrid, 256>>>(x, W[l], K, useX);
        k_aggregate<<<(Nn + 3) / 4, 256>>>(bia[l]);
        k_zero_stats<<<1, 256>>>();
        k_stats<<<(Nn + 63) / 64, 256>>>();
        k_norm_tanh<<<(Nn * 64 + 255) / 256, 256>>>(gam[l], bet[l]);
    }

    k_pool<<<Bg, 256>>>(batch, hidden);
    k_head<<<Bg, 512>>>(hidden, Wout, bout, out);
}

// round 15
// speedup vs baseline: 1.0340x; 1.0340x over previous
#include <cuda_runtime.h>
#include <cuda_bf16.h>

#define Nn 50000
#define Ee 800000
#define Dd 256
#define Fin 64
#define Bg 1000
#define BN_EPS 1e-5f

// ---------------- scratch (device globals; no allocation) ----------------
__device__ float g_mm[Nn * Dd];      // matmul output
__device__ float g_agg[Nn * Dd];     // aggregated
__device__ float g_h[Nn * Dd];       // layer activation
__device__ float g_ax[Nn * Fin];     // S @ x  (layer-0 pre-aggregated input)
__device__ int   g_cnt[Nn];          // in-degree (no self loop)
__device__ float g_dinv[Nn];         // rsqrt(deg+1)
__device__ int   g_off[Nn + 1];      // CSR row offsets
__device__ int   g_cur[Nn];          // scatter cursors
__device__ int   g_ssrc[Ee];         // src ids sorted by dst
__device__ float g_coef[Ee];         // dinv[src]*dinv[dst] sorted by dst
__device__ float g_sum[Dd];
__device__ float g_sumsq[Dd];

// ---------------- f32x2 helpers ----------------
__device__ __forceinline__ unsigned long long pack2(float x, float y) {
    unsigned long long r;
    asm("mov.b64 %0, {%1, %2};" : "=l"(r) : "f"(x), "f"(y));
    return r;
}
__device__ __forceinline__ void unpack2(unsigned long long v, float& x, float& y) {
    asm("mov.b64 {%0, %1}, %2;" : "=f"(x), "=f"(y) : "l"(v));
}
__device__ __forceinline__ void ffma2(unsigned long long& d, unsigned long long a,
                                      unsigned long long b) {
    asm("fma.rn.f32x2 %0, %1, %2, %0;" : "+l"(d) : "l"(a), "l"(b));
}

// ---------------- graph preprocessing ----------------
__global__ void k_zero_graph() {
    int i = blockIdx.x * blockDim.x + threadIdx.x;
    if (i < Nn) { g_cnt[i] = 0; g_cur[i] = 0; }
}

__global__ void k_degree(const int* __restrict__ ei) {
    int e = blockIdx.x * blockDim.x + threadIdx.x;
    if (e < Ee) atomicAdd(&g_cnt[ei[Ee + e]], 1);
}

__global__ void k_scan() {
    const int T = 1024;
    const int chunk = (Nn + T - 1) / T;
    __shared__ int s[T];
    int t = threadIdx.x;
    int beg = t * chunk;
    int end = beg + chunk; if (end > Nn) end = Nn;
    int loc = 0;
    for (int i = beg; i < end; i++) loc += g_cnt[i];
    s[t] = loc;
    __syncthreads();
    for (int d = 1; d < T; d <<= 1) {
        int v = (t >= d) ? s[t - d] : 0;
        __syncthreads();
        s[t] += v;
        __syncthreads();
    }
    int prefix = (t == 0) ? 0 : s[t - 1];
    for (int i = beg; i < end; i++) {
        g_off[i] = prefix;
        prefix += g_cnt[i];
    }
    if (t == T - 1) g_off[Nn] = prefix;
    for (int i = t; i < Nn; i += T) g_dinv[i] = rsqrtf(1.0f + (float)g_cnt[i]);
}

__global__ void k_scatter(const int* __restrict__ ei) {
    int e = blockIdx.x * blockDim.x + threadIdx.x;
    if (e >= Ee) return;
    int s = ei[e];
    int d = ei[Ee + e];
    int pos = g_off[d] + atomicAdd(&g_cur[d], 1);
    g_ssrc[pos] = s;
    g_coef[pos] = g_dinv[s] * g_dinv[d];
}

// ---------------- SGEMM (f32x2): C[N,Dd] = A[N,K] @ W[K,Dd] ----------------
// BM=128, BN=128, BK=16, 256 threads, 8x8 micro-tile as 8x4 f32x2 pairs.
// sel: 0 -> A = g_h (K=256), 1 -> A = g_ax (K=64)
__global__ __launch_bounds__(256, 2)
void k_gemm(const float* __restrict__ W, int K, int sel) {
    const int BM = 128, BNt = 128, BK = 16;
    __shared__ float As[BK][BM];
    __shared__ float Bs[BK][BNt];

    int bn = blockIdx.x;
    int bm = blockIdx.y;
    int tid = threadIdx.x;
    int tx = tid & 15, ty = tid >> 4;
    int rowBase = bm * BM;

    const float* Abase = sel ? g_ax : g_h;

    unsigned long long acc2[8][4];
#pragma unroll
    for (int i = 0; i < 8; i++)
#pragma unroll
        for (int j = 0; j < 4; j++) acc2[i][j] = 0ull;

    for (int k0 = 0; k0 < K; k0 += BK) {
        // A tile: 128 rows x 16 cols, transposed into As[k][m]
#pragma unroll
        for (int l = 0; l < 2; l++) {
            int idx = tid * 2 + l;        // 0..511
            int m = idx >> 2;             // 0..127
            int k4 = idx & 3;             // 0..3
            int grow = rowBase + m;
            float4 v = make_float4(0.f, 0.f, 0.f, 0.f);
            if (grow < Nn)
                v = *(const float4*)&Abase[(size_t)grow * K + k0 + k4 * 4];
            As[k4 * 4 + 0][m] = v.x;
            As[k4 * 4 + 1][m] = v.y;
            As[k4 * 4 + 2][m] = v.z;
            As[k4 * 4 + 3][m] = v.w;
        }
        // B tile: 16 x 128
#pragma unroll
        for (int l = 0; l < 2; l++) {
            int idx = tid * 2 + l;
            int k = idx >> 5;
            int n4 = idx & 31;
            float4 v = *(const float4*)&W[(size_t)(k0 + k) * Dd + bn * BNt + n4 * 4];
            *(float4*)&Bs[k][n4 * 4] = v;
        }
        __syncthreads();
#pragma unroll
        for (int k = 0; k < BK; k++) {
            float4 a0 = *(const float4*)&As[k][ty * 8];
            float4 a1 = *(const float4*)&As[k][ty * 8 + 4];
            const unsigned long long* bp = (const unsigned long long*)&Bs[k][tx * 8];
            unsigned long long b0 = bp[0], b1 = bp[1], b2 = bp[2], b3 = bp[3];
            unsigned long long A2[8];
            A2[0] = pack2(a0.x, a0.x); A2[1] = pack2(a0.y, a0.y);
            A2[2] = pack2(a0.z, a0.z); A2[3] = pack2(a0.w, a0.w);
            A2[4] = pack2(a1.x, a1.x); A2[5] = pack2(a1.y, a1.y);
            A2[6] = pack2(a1.z, a1.z); A2[7] = pack2(a1.w, a1.w);
#pragma unroll
            for (int i = 0; i < 8; i++) {
                ffma2(acc2[i][0], A2[i], b0);
                ffma2(acc2[i][1], A2[i], b1);
                ffma2(acc2[i][2], A2[i], b2);
                ffma2(acc2[i][3], A2[i], b3);
            }
        }
        __syncthreads();
    }
#pragma unroll
    for (int i = 0; i < 8; i++) {
        int grow = rowBase + ty * 8 + i;
        if (grow < Nn) {
            float4 v0, v1;
            unpack2(acc2[i][0], v0.x, v0.y);
            unpack2(acc2[i][1], v0.z, v0.w);
            unpack2(acc2[i][2], v1.x, v1.y);
            unpack2(acc2[i][3], v1.z, v1.w);
            float* dst = &g_mm[(size_t)grow * Dd + bn * BNt + tx * 8];
            *(float4*)dst = v0;
            *(float4*)(dst + 4) = v1;
        }
    }
}

// ---------------- aggregation on D=256: g_agg = S @ g_mm ----------------
__global__ void k_aggregate() {
    int node = blockIdx.x * 4 + (threadIdx.x >> 6);
    int lane = threadIdx.x & 63;
    if (node >= Nn) return;

    const float4* mmv = (const float4*)g_mm;
    float di = g_dinv[node];
    float4 acc = mmv[(size_t)node * 64 + lane];
    float sc = di * di;
    acc.x *= sc; acc.y *= sc; acc.z *= sc; acc.w *= sc;

    int s0 = g_off[node], s1 = g_off[node + 1];
    for (int k = s0; k < s1; k++) {
        int s = g_ssrc[k];
        float c = g_coef[k];
        float4 v = mmv[(size_t)s * 64 + lane];
        acc.x += c * v.x; acc.y += c * v.y; acc.z += c * v.z; acc.w += c * v.w;
    }
    ((float4*)g_agg)[(size_t)node * 64 + lane] = acc;
}

// ---------------- layer-0 aggregation on F=64: g_ax = S @ x ----------------
__global__ void k_aggregate_x(const float* __restrict__ x) {
    int node = blockIdx.x * 16 + (threadIdx.x >> 4);
    int lane = threadIdx.x & 15;
    if (node >= Nn) return;

    const float4* xv = (const float4*)x;
    float di = g_dinv[node];
    float4 acc = xv[(size_t)node * 16 + lane];
    float sc = di * di;
    acc.x *= sc; acc.y *= sc; acc.z *= sc; acc.w *= sc;

    int s0 = g_off[node], s1 = g_off[node + 1];
    for (int k = s0; k < s1; k++) {
        int s = g_ssrc[k];
        float c = g_coef[k];
        float4 v = xv[(size_t)s * 16 + lane];
        acc.x += c * v.x; acc.y += c * v.y; acc.z += c * v.z; acc.w += c * v.w;
    }
    ((float4*)g_ax)[(size_t)node * 16 + lane] = acc;
}

// ---------------- batch-norm ----------------
__global__ void k_zero_stats() {
    int t = threadIdx.x;
    if (t < Dd) { g_sum[t] = 0.f; g_sumsq[t] = 0.f; }
}

// fromMM: 1 -> stats over g_mm (layer 0), 0 -> over g_agg
__global__ void k_stats(int fromMM) {
    const float* src = fromMM ? g_mm : g_agg;
    int f = threadIdx.x;
    int r0 = blockIdx.x * 64;
    int r1 = r0 + 64; if (r1 > Nn) r1 = Nn;
    float sm = 0.f, sq = 0.f;
    for (int r = r0; r < r1; r++) {
        float v = src[(size_t)r * Dd + f];
        sm += v;
        sq += v * v;
    }
    atomicAdd(&g_sum[f], sm);
    atomicAdd(&g_sumsq[f], sq);
}

__global__ void k_norm_tanh(const float* __restrict__ gamma, const float* __restrict__ beta,
                            int fromMM) {
    const float4* src = fromMM ? (const float4*)g_mm : (const float4*)g_agg;
    int idx = blockIdx.x * blockDim.x + threadIdx.x;
    if (idx >= Nn * 64) return;
    int c4 = idx & 63;
    int f = c4 * 4;
    float4 v = src[idx];
    const float invN = 1.0f / (float)Nn;
    float r[4] = {v.x, v.y, v.z, v.w};
#pragma unroll
    for (int j = 0; j < 4; j++) {
        float mu = g_sum[f + j] * invN;
        float var = g_sumsq[f + j] * invN - mu * mu;
        float sc = gamma[f + j] * rsqrtf(var + BN_EPS);
        r[j] = tanhf((r[j] - mu) * sc + beta[f + j]);
    }
    ((float4*)g_h)[idx] = make_float4(r[0], r[1], r[2], r[3]);
}

// ---------------- pooling + head ----------------
__device__ __forceinline__ int lower_bound_dev(const int* a, int n, int key) {
    int lo = 0, hi = n;
    while (lo < hi) {
        int mid = (lo + hi) >> 1;
        if (a[mid] < key) lo = mid + 1; else hi = mid;
    }
    return lo;
}

__global__ void k_pool(const int* __restrict__ batch, float* __restrict__ hidden) {
    __shared__ int s_lo, s_hi;
    int g = blockIdx.x;
    int f = threadIdx.x;
    if (f == 0) s_lo = lower_bound_dev(batch, Nn, g);
    if (f == 1) s_hi = lower_bound_dev(batch, Nn, g + 1);
    __syncthreads();
    int lo = s_lo, hi = s_hi;
    float mx = -3.4e38f, sm = 0.f;
    for (int n = lo; n < hi; n++) {
        float v = g_h[(size_t)n * Dd + f];
        mx = fmaxf(mx, v);
        sm += v;
    }
    float cnt = (float)(hi - lo);
    hidden[(size_t)g * 512 + f] = mx;
    hidden[(size_t)g * 512 + 256 + f] = sm / cnt;
}

__global__ void k_head(const float* __restrict__ hidden, const float* __restrict__ Wout,
                       const float* __restrict__ bout, float* __restrict__ out) {
    __shared__ float sm[512];
    int g = blockIdx.x;
    int t = threadIdx.x;
    sm[t] = hidden[(size_t)g * 512 + t] * Wout[t];
    __syncthreads();
    for (int s = 256; s > 0; s >>= 1) {
        if (t < s) sm[t] += sm[t + s];
        __syncthreads();
    }
    if (t == 0) out[g] = sm[0] + bout[0];
}

// ---------------- launch ----------------
extern "C" void kernel_launch(void* const* d_in, const int* in_sizes, int n_in,
                              void* d_out, int out_size) {
    const float* x     = (const float*)d_in[0];
    const int*   ei    = (const int*)d_in[1];
    const int*   batch = (const int*)d_in[2];
    const float* W[4]   = {(const float*)d_in[4], (const float*)d_in[6],
                           (const float*)d_in[8], (const float*)d_in[10]};
    const float* gam[4] = {(const float*)d_in[12], (const float*)d_in[14],
                           (const float*)d_in[16], (const float*)d_in[18]};
    const float* bet[4] = {(const float*)d_in[13], (const float*)d_in[15],
                           (const float*)d_in[17], (const float*)d_in[19]};
    const float* Wout = (const float*)d_in[20];
    const float* bout = (const float*)d_in[21];

    float* out    = (float*)d_out;        // [Bg]
    float* hidden = out + Bg;             // [Bg, 512]

    // graph preprocessing (CSR build)
    k_zero_graph<<<(Nn + 255) / 256, 256>>>();
    k_degree<<<(Ee + 255) / 256, 256>>>(ei);
    k_scan<<<1, 1024>>>();
    k_scatter<<<(Ee + 255) / 256, 256>>>(ei);

    dim3 gemmGrid(Dd / 128, (Nn + 127) / 128);

    // Layer 0: (S @ x) @ W0  — aggregate in 64-dim first (4x less gather traffic).
    // GCN biases are dropped everywhere: BN(z + b) == BN(z) exactly.
    k_aggregate_x<<<(Nn + 15) / 16, 256>>>(x);
    k_gemm<<<gemmGrid, 256>>>(W[0], Fin, 1);
    k_zero_stats<<<1, 256>>>();
    k_stats<<<(Nn + 63) / 64, 256>>>(1);
    k_norm_tanh<<<(Nn * 64 + 255) / 256, 256>>>(gam[0], bet[0], 1);

    // Layers 1-3: S @ (h @ W)
    for (int l = 1; l < 4; l++) {
        k_gemm<<<gemmGrid, 256>>>(W[l], Dd, 0);
        k_aggregate<<<(Nn + 3) / 4, 256>>>();
        k_zero_stats<<<1, 256>>>();
        k_stats<<<(Nn + 63) / 64, 256>>>(0);
        k_norm_tanh<<<(Nn * 64 + 255) / 256, 256>>>(gam[l], bet[l], 0);
    }

    k_pool<<<Bg, 256>>>(batch, hidden);
    k_head<<<Bg, 512>>>(hidden, Wout, bout, out);
}